// round 3
// baseline (speedup 1.0000x reference)
#include <cuda_runtime.h>
#include <cuda_bf16.h>
#include <math.h>
#include <stdint.h>

#define NROWS 1024
#define NV    32000
#define LSRC  320
#define CTXL  256
#define STN   32
#define NTOT  32320
#define HDIM  512
#define SCALE 0.04419417382415922f   // 1/sqrt(512)

__device__ float g_logits[(size_t)NROWS * NTOT];
__device__ float g_rmax[NROWS];
__device__ float g_rsum[NROWS];

// ---------------------------------------------------------------------------
// bf16 mma.sync m16n8k16 wrapper
// ---------------------------------------------------------------------------
__device__ __forceinline__ void mma16816(float* c, const uint32_t* a, const uint32_t* b) {
    asm volatile(
        "mma.sync.aligned.m16n8k16.row.col.f32.bf16.bf16.f32 "
        "{%0,%1,%2,%3}, {%4,%5,%6,%7}, {%8,%9}, {%0,%1,%2,%3};\n"
        : "+f"(c[0]), "+f"(c[1]), "+f"(c[2]), "+f"(c[3])
        : "r"(a[0]), "r"(a[1]), "r"(a[2]), "r"(a[3]),
          "r"(b[0]), "r"(b[1]));
}

// ---------------------------------------------------------------------------
// Kernel 1: gen logits GEMM  (dec_out[1024,512] @ W[512,32000] + b) * SCALE
//   BM=128, BN=128, BK=32, 256 threads (8 warps, 2x4 warp grid, warp=64x32)
//   fp32 loaded from GMEM, converted to bf16 on the way into smem.
//   grid = (8 M-tiles fastest, 250 N-tiles) -> adjacent blocks share the same
//   W tile so W streams from DRAM ~once (65 MB < 126 MB L2).
// ---------------------------------------------------------------------------
#define BM 128
#define BN 128
#define BK 32
#define SAP 34   // smem pitch (elems) for A  [row][k]
#define SBP 34   // smem pitch (elems) for Bt [n][k]

__global__ __launch_bounds__(256, 1)
void gen_gemm_kernel(const float* __restrict__ A, const float* __restrict__ W,
                     const float* __restrict__ bias)
{
    __shared__ __nv_bfloat16 sA[2][BM * SAP];
    __shared__ __nv_bfloat16 sB[2][BN * SBP];

    const int tid  = threadIdx.x;
    const int warp = tid >> 5, lane = tid & 31;
    const int m0 = blockIdx.x * BM;
    const int n0 = blockIdx.y * BN;
    const int wm = (warp >> 2) * 64;
    const int wn = (warp & 3) * 32;

    // A load mapping: 4 passes of 32 rows, 8 float4 per row
    const int a_r = tid >> 3;          // 0..31
    const int a_c = (tid & 7) * 4;     // 0..28
    // B load mapping: each thread owns one n-column, 16 consecutive k's
    const int b_n = tid & 127;
    const int b_k = (tid >> 7) * 16;

    float4 aReg[4];
    float  bReg[16];

    // ---- prologue: load k-tile 0 ----
    {
        const int k0 = 0;
        #pragma unroll
        for (int p = 0; p < 4; ++p)
            aReg[p] = *(const float4*)(A + (size_t)(m0 + a_r + 32 * p) * HDIM + k0 + a_c);
        #pragma unroll
        for (int j = 0; j < 16; ++j)
            bReg[j] = W[(size_t)(k0 + b_k + j) * NV + n0 + b_n];
        // store to buf 0
        #pragma unroll
        for (int p = 0; p < 4; ++p) {
            __nv_bfloat162* dst = (__nv_bfloat162*)&sA[0][(a_r + 32 * p) * SAP + a_c];
            dst[0] = __floats2bfloat162_rn(aReg[p].x, aReg[p].y);
            dst[1] = __floats2bfloat162_rn(aReg[p].z, aReg[p].w);
        }
        __nv_bfloat162* dstB = (__nv_bfloat162*)&sB[0][b_n * SBP + b_k];
        #pragma unroll
        for (int j = 0; j < 8; ++j)
            dstB[j] = __floats2bfloat162_rn(bReg[2 * j], bReg[2 * j + 1]);
    }
    __syncthreads();

    float acc[4][4][4];
    #pragma unroll
    for (int i = 0; i < 4; ++i)
        #pragma unroll
        for (int j = 0; j < 4; ++j)
            #pragma unroll
            for (int q = 0; q < 4; ++q) acc[i][j][q] = 0.f;

    const int KT = HDIM / BK;   // 16
    for (int kt = 0; kt < KT; ++kt) {
        const int buf = kt & 1;
        if (kt < KT - 1) {
            const int k0 = (kt + 1) * BK;
            #pragma unroll
            for (int p = 0; p < 4; ++p)
                aReg[p] = *(const float4*)(A + (size_t)(m0 + a_r + 32 * p) * HDIM + k0 + a_c);
            #pragma unroll
            for (int j = 0; j < 16; ++j)
                bReg[j] = W[(size_t)(k0 + b_k + j) * NV + n0 + b_n];
        }

        // compute on buf
        #pragma unroll
        for (int kk = 0; kk < 2; ++kk) {
            uint32_t af[4][4];
            uint32_t bfr[4][2];
            const int c0 = kk * 16 + (lane & 3) * 2;
            #pragma unroll
            for (int mi = 0; mi < 4; ++mi) {
                const int r0 = wm + mi * 16 + (lane >> 2);
                const __nv_bfloat16* base = &sA[buf][r0 * SAP];
                af[mi][0] = *(const uint32_t*)(base + c0);
                af[mi][1] = *(const uint32_t*)(base + SAP * 8 + c0);
                af[mi][2] = *(const uint32_t*)(base + c0 + 8);
                af[mi][3] = *(const uint32_t*)(base + SAP * 8 + c0 + 8);
            }
            #pragma unroll
            for (int ni = 0; ni < 4; ++ni) {
                const int cn = wn + ni * 8 + (lane >> 2);
                const __nv_bfloat16* base = &sB[buf][cn * SBP];
                bfr[ni][0] = *(const uint32_t*)(base + c0);
                bfr[ni][1] = *(const uint32_t*)(base + c0 + 8);
            }
            #pragma unroll
            for (int mi = 0; mi < 4; ++mi)
                #pragma unroll
                for (int ni = 0; ni < 4; ++ni)
                    mma16816(acc[mi][ni], af[mi], bfr[ni]);
        }

        if (kt < KT - 1) {
            const int nb = 1 - buf;
            #pragma unroll
            for (int p = 0; p < 4; ++p) {
                __nv_bfloat162* dst = (__nv_bfloat162*)&sA[nb][(a_r + 32 * p) * SAP + a_c];
                dst[0] = __floats2bfloat162_rn(aReg[p].x, aReg[p].y);
                dst[1] = __floats2bfloat162_rn(aReg[p].z, aReg[p].w);
            }
            __nv_bfloat162* dstB = (__nv_bfloat162*)&sB[nb][b_n * SBP + b_k];
            #pragma unroll
            for (int j = 0; j < 8; ++j)
                dstB[j] = __floats2bfloat162_rn(bReg[2 * j], bReg[2 * j + 1]);
        }
        __syncthreads();
    }

    // epilogue: (acc + bias) * SCALE  ->  g_logits[:, 0:32000]
    const int tg = lane & 3, gr = lane >> 2;
    #pragma unroll
    for (int mi = 0; mi < 4; ++mi) {
        const int row = m0 + wm + mi * 16 + gr;
        #pragma unroll
        for (int ni = 0; ni < 4; ++ni) {
            const int col = n0 + wn + ni * 8 + tg * 2;
            const float b0 = bias[col], b1 = bias[col + 1];
            float2 v0, v1;
            v0.x = (acc[mi][ni][0] + b0) * SCALE;
            v0.y = (acc[mi][ni][1] + b1) * SCALE;
            v1.x = (acc[mi][ni][2] + b0) * SCALE;
            v1.y = (acc[mi][ni][3] + b1) * SCALE;
            *(float2*)(g_logits + (size_t)row * NTOT + col)       = v0;
            *(float2*)(g_logits + (size_t)(row + 8) * NTOT + col) = v1;
        }
    }
}

// ---------------------------------------------------------------------------
// Kernel 2: copy logits (fp32, precision-critical, tiny GEMM)
//   per block: 64 l-rows x 64 s-cols for one b; grid (5 s-tiles, 2 l-tiles, 8 b)
// ---------------------------------------------------------------------------
__global__ __launch_bounds__(256, 1)
void copy_logit_kernel(const float* __restrict__ dec, const float* __restrict__ src,
                       const int* __restrict__ mask)
{
    __shared__ float sA2[2][64][17];
    __shared__ float sB2[2][64][17];

    const int st = blockIdx.x, lt = blockIdx.y, b = blockIdx.z;
    const int tid = threadIdx.x;
    const int lr = tid >> 2;          // 0..63
    const int lc = (tid & 3) * 4;     // 0,4,8,12
    const int ty = tid >> 4, tx = tid & 15;

    const float* Ag = dec + (size_t)(b * 128 + lt * 64) * HDIM;
    const float* Bg = src + (size_t)(b * LSRC + st * 64) * HDIM;

    float4 ra, rb;
    // prologue
    ra = *(const float4*)(Ag + (size_t)lr * HDIM + lc);
    rb = *(const float4*)(Bg + (size_t)lr * HDIM + lc);
    sA2[0][lr][lc + 0] = ra.x; sA2[0][lr][lc + 1] = ra.y;
    sA2[0][lr][lc + 2] = ra.z; sA2[0][lr][lc + 3] = ra.w;
    sB2[0][lr][lc + 0] = rb.x; sB2[0][lr][lc + 1] = rb.y;
    sB2[0][lr][lc + 2] = rb.z; sB2[0][lr][lc + 3] = rb.w;
    __syncthreads();

    float acc[4][4] = {};

    for (int kt = 0; kt < 32; ++kt) {
        const int buf = kt & 1;
        if (kt < 31) {
            const int k0 = (kt + 1) * 16;
            ra = *(const float4*)(Ag + (size_t)lr * HDIM + k0 + lc);
            rb = *(const float4*)(Bg + (size_t)lr * HDIM + k0 + lc);
        }
        #pragma unroll
        for (int k = 0; k < 16; ++k) {
            float a0 = sA2[buf][ty * 4 + 0][k];
            float a1 = sA2[buf][ty * 4 + 1][k];
            float a2 = sA2[buf][ty * 4 + 2][k];
            float a3 = sA2[buf][ty * 4 + 3][k];
            float b0 = sB2[buf][tx * 4 + 0][k];
            float b1 = sB2[buf][tx * 4 + 1][k];
            float b2 = sB2[buf][tx * 4 + 2][k];
            float b3 = sB2[buf][tx * 4 + 3][k];
            acc[0][0] += a0 * b0; acc[0][1] += a0 * b1; acc[0][2] += a0 * b2; acc[0][3] += a0 * b3;
            acc[1][0] += a1 * b0; acc[1][1] += a1 * b1; acc[1][2] += a1 * b2; acc[1][3] += a1 * b3;
            acc[2][0] += a2 * b0; acc[2][1] += a2 * b1; acc[2][2] += a2 * b2; acc[2][3] += a2 * b3;
            acc[3][0] += a3 * b0; acc[3][1] += a3 * b1; acc[3][2] += a3 * b2; acc[3][3] += a3 * b3;
        }
        if (kt < 31) {
            const int nb = 1 - buf;
            sA2[nb][lr][lc + 0] = ra.x; sA2[nb][lr][lc + 1] = ra.y;
            sA2[nb][lr][lc + 2] = ra.z; sA2[nb][lr][lc + 3] = ra.w;
            sB2[nb][lr][lc + 0] = rb.x; sB2[nb][lr][lc + 1] = rb.y;
            sB2[nb][lr][lc + 2] = rb.z; sB2[nb][lr][lc + 3] = rb.w;
        }
        __syncthreads();
    }

    #pragma unroll
    for (int i = 0; i < 4; ++i) {
        const int row = b * 128 + lt * 64 + ty * 4 + i;
        #pragma unroll
        for (int j = 0; j < 4; ++j) {
            const int sg = st * 64 + tx * 4 + j;
            float v = (mask[b * LSRC + sg] == 0) ? -1e9f : acc[i][j];
            g_logits[(size_t)row * NTOT + NV + sg] = v * SCALE;
        }
    }
}

// ---------------------------------------------------------------------------
// Kernel 3: per-row online softmax stats (max, sum of exp) over 32320 cols
// ---------------------------------------------------------------------------
__device__ __forceinline__ void sm_combine(float& m, float& s, float m2, float s2) {
    float M = fmaxf(m, m2);
    s = s * expf(m - M) + s2 * expf(m2 - M);
    m = M;
}

__global__ __launch_bounds__(256)
void stats_kernel()
{
    const int row = blockIdx.x;
    const int tid = threadIdx.x;
    const float4* p = (const float4*)(g_logits + (size_t)row * NTOT);

    float m = -3.4e38f, s = 0.f;
    for (int i = tid; i < NTOT / 4; i += 256) {
        float4 v = p[i];
        #pragma unroll
        for (int q = 0; q < 4; ++q) {
            float x = (q == 0) ? v.x : (q == 1) ? v.y : (q == 2) ? v.z : v.w;
            if (x > m) { s = s * expf(m - x) + 1.f; m = x; }
            else        { s += expf(x - m); }
        }
    }
    // warp reduce
    #pragma unroll
    for (int off = 16; off > 0; off >>= 1) {
        float m2 = __shfl_xor_sync(0xffffffffu, m, off);
        float s2 = __shfl_xor_sync(0xffffffffu, s, off);
        sm_combine(m, s, m2, s2);
    }
    __shared__ float sm[8], ss[8];
    if ((tid & 31) == 0) { sm[tid >> 5] = m; ss[tid >> 5] = s; }
    __syncthreads();
    if (tid == 0) {
        float M = sm[0], S = ss[0];
        #pragma unroll
        for (int w = 1; w < 8; ++w) sm_combine(M, S, sm[w], ss[w]);
        g_rmax[row] = M;
        g_rsum[row] = S;
    }
}

// ---------------------------------------------------------------------------
// Kernel 4: write gen probs to output
// ---------------------------------------------------------------------------
__global__ __launch_bounds__(256)
void prob_kernel(float* __restrict__ out)
{
    const int row = blockIdx.y;
    const int i = blockIdx.x * 256 + threadIdx.x;   // float4 index
    if (i >= NV / 4) return;
    const float m   = g_rmax[row];
    const float inv = 1.f / g_rsum[row];
    float4 v = *(const float4*)(g_logits + (size_t)row * NTOT + i * 4);
    v.x = expf(v.x - m) * inv;
    v.y = expf(v.y - m) * inv;
    v.z = expf(v.z - m) * inv;
    v.w = expf(v.w - m) * inv;
    *(float4*)(out + (size_t)row * NV + i * 4) = v;
}

// ---------------------------------------------------------------------------
// Kernel 5: scatter copy probs into output vocab positions
// ---------------------------------------------------------------------------
__global__ __launch_bounds__(320)
void scatter_kernel(const int* __restrict__ context, const int* __restrict__ tp,
                    const int* __restrict__ action, const int* __restrict__ loc2glo,
                    float* __restrict__ out)
{
    const int row = blockIdx.x;
    const int b   = row >> 7;
    const int s   = threadIdx.x;   // 0..319
    const float m   = g_rmax[row];
    const float inv = 1.f / g_rsum[row];
    const float x = g_logits[(size_t)row * NTOT + NV + s];
    const float p = expf(x - m) * inv;   // masked -> exp(huge negative)=0

    int idx;
    if (s < CTXL)            idx = context[b * CTXL + s];
    else if (s < CTXL + STN) idx = loc2glo[tp[b * STN + (s - CTXL)]];
    else                     idx = loc2glo[action[b * STN + (s - CTXL - STN)]];

    atomicAdd(out + (size_t)row * NV + idx, p);
}

// ---------------------------------------------------------------------------
extern "C" void kernel_launch(void* const* d_in, const int* in_sizes, int n_in,
                              void* d_out, int out_size)
{
    const float* dec     = (const float*)d_in[0];  // (8,128,512)
    const float* src     = (const float*)d_in[1];  // (8,320,512)
    const float* W       = (const float*)d_in[2];  // (512,32000)
    const float* bgen    = (const float*)d_in[3];  // (32000,)
    const int*   mask    = (const int*)d_in[4];    // (8,1,320)
    const int*   context = (const int*)d_in[5];    // (8,256)
    const int*   tp      = (const int*)d_in[6];    // (8,32)
    const int*   action  = (const int*)d_in[7];    // (8,32)
    const int*   loc2glo = (const int*)d_in[8];    // (4096,)
    float*       out     = (float*)d_out;          // (8,128,32000)

    copy_logit_kernel<<<dim3(5, 2, 8), 256>>>(dec, src, mask);
    gen_gemm_kernel<<<dim3(8, 250), 256>>>(dec, W, bgen);
    stats_kernel<<<1024, 256>>>();
    prob_kernel<<<dim3(32, 1024), 256>>>(out);
    scatter_kernel<<<1024, 320>>>(context, tp, action, loc2glo, out);
}

// round 4
// speedup vs baseline: 1.2606x; 1.2606x over previous
#include <cuda_runtime.h>
#include <cuda_bf16.h>
#include <math.h>
#include <stdint.h>

#define NROWS 1024
#define NV    32000
#define LSRC  320
#define CTXL  256
#define STN   32
#define HDIM  512
#define SCALE 0.04419417382415922f   // 1/sqrt(512)

__device__ float g_copy[(size_t)NROWS * LSRC];   // unnormalized exp of copy logits
__device__ float g_rsum[NROWS];                  // per-row sum of exps (atomic)

// ---------------------------------------------------------------------------
// bf16 mma.sync m16n8k16 wrapper
// ---------------------------------------------------------------------------
__device__ __forceinline__ void mma16816(float* c, const uint32_t* a, const uint32_t* b) {
    asm volatile(
        "mma.sync.aligned.m16n8k16.row.col.f32.bf16.bf16.f32 "
        "{%0,%1,%2,%3}, {%4,%5,%6,%7}, {%8,%9}, {%0,%1,%2,%3};\n"
        : "+f"(c[0]), "+f"(c[1]), "+f"(c[2]), "+f"(c[3])
        : "r"(a[0]), "r"(a[1]), "r"(a[2]), "r"(a[3]),
          "r"(b[0]), "r"(b[1]));
}

// ---------------------------------------------------------------------------
// Kernel 0: zero the row-sum accumulators
// ---------------------------------------------------------------------------
__global__ void zero_rsum_kernel() {
    g_rsum[blockIdx.x * 256 + threadIdx.x] = 0.f;
}

// ---------------------------------------------------------------------------
// Kernel 1: gen GEMM fused with exp + row-sum.
//   out[row, col] = exp((dec@W + b) * SCALE)   (unnormalized)
//   g_rsum[row]  += partial sums (atomic)
//   BM=128, BN=128, BK=32, 512 threads (16 warps, 4x4 grid, warp tile 32x32)
//   grid = (8 M-tiles fastest, 250 N-tiles) so concurrent blocks share W tiles
//   (65MB W streams from DRAM once, re-read from L2).
// ---------------------------------------------------------------------------
#define BM 128
#define BN 128
#define BK 32
#define SAP 34
#define SBP 34

__global__ __launch_bounds__(512, 1)
void gen_gemm_kernel(const float* __restrict__ A, const float* __restrict__ W,
                     const float* __restrict__ bias, float* __restrict__ out)
{
    __shared__ __nv_bfloat16 sA[2][BM * SAP];
    __shared__ __nv_bfloat16 sB[2][BN * SBP];

    const int tid  = threadIdx.x;
    const int warp = tid >> 5, lane = tid & 31;
    const int m0 = blockIdx.x * BM;
    const int n0 = blockIdx.y * BN;
    const int wm = (warp >> 2) * 32;
    const int wn = (warp & 3) * 32;

    // A load: each thread 8 floats (2 float4) of one row
    const int a_r = tid >> 2;          // 0..127
    const int a_c = (tid & 3) * 8;     // 0,8,16,24
    // B load: each thread one n-column, 8 consecutive k's
    const int b_n = tid & 127;
    const int b_k = (tid >> 7) * 8;    // 0,8,16,24

    float4 aReg0, aReg1;
    float  bReg[8];

    // ---- prologue: k-tile 0 ----
    {
        aReg0 = *(const float4*)(A + (size_t)(m0 + a_r) * HDIM + a_c);
        aReg1 = *(const float4*)(A + (size_t)(m0 + a_r) * HDIM + a_c + 4);
        #pragma unroll
        for (int j = 0; j < 8; ++j)
            bReg[j] = W[(size_t)(b_k + j) * NV + n0 + b_n];
        __nv_bfloat162* dA = (__nv_bfloat162*)&sA[0][a_r * SAP + a_c];
        dA[0] = __floats2bfloat162_rn(aReg0.x, aReg0.y);
        dA[1] = __floats2bfloat162_rn(aReg0.z, aReg0.w);
        dA[2] = __floats2bfloat162_rn(aReg1.x, aReg1.y);
        dA[3] = __floats2bfloat162_rn(aReg1.z, aReg1.w);
        __nv_bfloat162* dB = (__nv_bfloat162*)&sB[0][b_n * SBP + b_k];
        #pragma unroll
        for (int j = 0; j < 4; ++j)
            dB[j] = __floats2bfloat162_rn(bReg[2 * j], bReg[2 * j + 1]);
    }
    __syncthreads();

    float acc[2][4][4];
    #pragma unroll
    for (int i = 0; i < 2; ++i)
        #pragma unroll
        for (int j = 0; j < 4; ++j)
            #pragma unroll
            for (int q = 0; q < 4; ++q) acc[i][j][q] = 0.f;

    const int KT = HDIM / BK;   // 16
    for (int kt = 0; kt < KT; ++kt) {
        const int buf = kt & 1;
        if (kt < KT - 1) {
            const int k0 = (kt + 1) * BK;
            aReg0 = *(const float4*)(A + (size_t)(m0 + a_r) * HDIM + k0 + a_c);
            aReg1 = *(const float4*)(A + (size_t)(m0 + a_r) * HDIM + k0 + a_c + 4);
            #pragma unroll
            for (int j = 0; j < 8; ++j)
                bReg[j] = W[(size_t)(k0 + b_k + j) * NV + n0 + b_n];
        }

        #pragma unroll
        for (int kk = 0; kk < 2; ++kk) {
            uint32_t af[2][4];
            uint32_t bfr[4][2];
            const int c0 = kk * 16 + (lane & 3) * 2;
            #pragma unroll
            for (int mi = 0; mi < 2; ++mi) {
                const int r0 = wm + mi * 16 + (lane >> 2);
                const __nv_bfloat16* base = &sA[buf][r0 * SAP];
                af[mi][0] = *(const uint32_t*)(base + c0);
                af[mi][1] = *(const uint32_t*)(base + SAP * 8 + c0);
                af[mi][2] = *(const uint32_t*)(base + c0 + 8);
                af[mi][3] = *(const uint32_t*)(base + SAP * 8 + c0 + 8);
            }
            #pragma unroll
            for (int ni = 0; ni < 4; ++ni) {
                const int cn = wn + ni * 8 + (lane >> 2);
                const __nv_bfloat16* base = &sB[buf][cn * SBP];
                bfr[ni][0] = *(const uint32_t*)(base + c0);
                bfr[ni][1] = *(const uint32_t*)(base + c0 + 8);
            }
            #pragma unroll
            for (int mi = 0; mi < 2; ++mi)
                #pragma unroll
                for (int ni = 0; ni < 4; ++ni)
                    mma16816(acc[mi][ni], af[mi], bfr[ni]);
        }

        if (kt < KT - 1) {
            const int nb = 1 - buf;
            __nv_bfloat162* dA = (__nv_bfloat162*)&sA[nb][a_r * SAP + a_c];
            dA[0] = __floats2bfloat162_rn(aReg0.x, aReg0.y);
            dA[1] = __floats2bfloat162_rn(aReg0.z, aReg0.w);
            dA[2] = __floats2bfloat162_rn(aReg1.x, aReg1.y);
            dA[3] = __floats2bfloat162_rn(aReg1.z, aReg1.w);
            __nv_bfloat162* dB = (__nv_bfloat162*)&sB[nb][b_n * SBP + b_k];
            #pragma unroll
            for (int j = 0; j < 4; ++j)
                dB[j] = __floats2bfloat162_rn(bReg[2 * j], bReg[2 * j + 1]);
        }
        __syncthreads();
    }

    // epilogue: e = exp((acc + bias) * SCALE) -> out ; row-sum partials -> g_rsum
    const int tg = lane & 3, gr = lane >> 2;
    #pragma unroll
    for (int mi = 0; mi < 2; ++mi) {
        const int row = m0 + wm + mi * 16 + gr;
        float rs0 = 0.f, rs1 = 0.f;
        #pragma unroll
        for (int ni = 0; ni < 4; ++ni) {
            const int col = n0 + wn + ni * 8 + tg * 2;
            const float b0 = bias[col], b1 = bias[col + 1];
            float e00 = __expf((acc[mi][ni][0] + b0) * SCALE);
            float e01 = __expf((acc[mi][ni][1] + b1) * SCALE);
            float e10 = __expf((acc[mi][ni][2] + b0) * SCALE);
            float e11 = __expf((acc[mi][ni][3] + b1) * SCALE);
            rs0 += e00 + e01;
            rs1 += e10 + e11;
            float2 v0 = {e00, e01}, v1 = {e10, e11};
            *(float2*)(out + (size_t)row * NV + col)       = v0;
            *(float2*)(out + (size_t)(row + 8) * NV + col) = v1;
        }
        // reduce over the 4 lanes of the quad (same row group)
        rs0 += __shfl_xor_sync(0xffffffffu, rs0, 1);
        rs0 += __shfl_xor_sync(0xffffffffu, rs0, 2);
        rs1 += __shfl_xor_sync(0xffffffffu, rs1, 1);
        rs1 += __shfl_xor_sync(0xffffffffu, rs1, 2);
        if (tg == 0) {
            atomicAdd(&g_rsum[row], rs0);
            atomicAdd(&g_rsum[row + 8], rs1);
        }
    }
}

// ---------------------------------------------------------------------------
// Kernel 2: copy logits (fp32), fused exp + mask + row-sum partials.
//   e = mask ? exp(dot * SCALE) : 0   -> g_copy ; sums -> g_rsum
// ---------------------------------------------------------------------------
__global__ __launch_bounds__(256, 1)
void copy_logit_kernel(const float* __restrict__ dec, const float* __restrict__ src,
                       const int* __restrict__ mask)
{
    __shared__ float sA2[2][64][17];
    __shared__ float sB2[2][64][17];

    const int st = blockIdx.x, lt = blockIdx.y, b = blockIdx.z;
    const int tid = threadIdx.x;
    const int lr = tid >> 2;
    const int lc = (tid & 3) * 4;
    const int ty = tid >> 4, tx = tid & 15;

    const float* Ag = dec + (size_t)(b * 128 + lt * 64) * HDIM;
    const float* Bg = src + (size_t)(b * LSRC + st * 64) * HDIM;

    float4 ra, rb;
    ra = *(const float4*)(Ag + (size_t)lr * HDIM + lc);
    rb = *(const float4*)(Bg + (size_t)lr * HDIM + lc);
    sA2[0][lr][lc + 0] = ra.x; sA2[0][lr][lc + 1] = ra.y;
    sA2[0][lr][lc + 2] = ra.z; sA2[0][lr][lc + 3] = ra.w;
    sB2[0][lr][lc + 0] = rb.x; sB2[0][lr][lc + 1] = rb.y;
    sB2[0][lr][lc + 2] = rb.z; sB2[0][lr][lc + 3] = rb.w;
    __syncthreads();

    float acc[4][4] = {};

    for (int kt = 0; kt < 32; ++kt) {
        const int buf = kt & 1;
        if (kt < 31) {
            const int k0 = (kt + 1) * 16;
            ra = *(const float4*)(Ag + (size_t)lr * HDIM + k0 + lc);
            rb = *(const float4*)(Bg + (size_t)lr * HDIM + k0 + lc);
        }
        #pragma unroll
        for (int k = 0; k < 16; ++k) {
            float a0 = sA2[buf][ty * 4 + 0][k];
            float a1 = sA2[buf][ty * 4 + 1][k];
            float a2 = sA2[buf][ty * 4 + 2][k];
            float a3 = sA2[buf][ty * 4 + 3][k];
            float b0 = sB2[buf][tx * 4 + 0][k];
            float b1 = sB2[buf][tx * 4 + 1][k];
            float b2 = sB2[buf][tx * 4 + 2][k];
            float b3 = sB2[buf][tx * 4 + 3][k];
            acc[0][0] += a0 * b0; acc[0][1] += a0 * b1; acc[0][2] += a0 * b2; acc[0][3] += a0 * b3;
            acc[1][0] += a1 * b0; acc[1][1] += a1 * b1; acc[1][2] += a1 * b2; acc[1][3] += a1 * b3;
            acc[2][0] += a2 * b0; acc[2][1] += a2 * b1; acc[2][2] += a2 * b2; acc[2][3] += a2 * b3;
            acc[3][0] += a3 * b0; acc[3][1] += a3 * b1; acc[3][2] += a3 * b2; acc[3][3] += a3 * b3;
        }
        if (kt < 31) {
            const int nb = 1 - buf;
            sA2[nb][lr][lc + 0] = ra.x; sA2[nb][lr][lc + 1] = ra.y;
            sA2[nb][lr][lc + 2] = ra.z; sA2[nb][lr][lc + 3] = ra.w;
            sB2[nb][lr][lc + 0] = rb.x; sB2[nb][lr][lc + 1] = rb.y;
            sB2[nb][lr][lc + 2] = rb.z; sB2[nb][lr][lc + 3] = rb.w;
        }
        __syncthreads();
    }

    #pragma unroll
    for (int i = 0; i < 4; ++i) {
        const int row = b * 128 + lt * 64 + ty * 4 + i;
        float rs = 0.f;
        #pragma unroll
        for (int j = 0; j < 4; ++j) {
            const int sg = st * 64 + tx * 4 + j;
            float e = (mask[b * LSRC + sg] == 0) ? 0.f : __expf(acc[i][j] * SCALE);
            g_copy[(size_t)row * LSRC + sg] = e;
            rs += e;
        }
        // reduce across the 16 tx-lanes (stay within the 16-lane half-warp)
        #pragma unroll
        for (int off = 8; off > 0; off >>= 1)
            rs += __shfl_xor_sync(0xffffffffu, rs, off);
        if (tx == 0) atomicAdd(&g_rsum[row], rs);
    }
}

// ---------------------------------------------------------------------------
// Kernel 3: scatter raw copy exps into out (runs before normalize)
// ---------------------------------------------------------------------------
__global__ __launch_bounds__(320)
void scatter_kernel(const int* __restrict__ context, const int* __restrict__ tp,
                    const int* __restrict__ action, const int* __restrict__ loc2glo,
                    float* __restrict__ out)
{
    const int row = blockIdx.x;
    const int b   = row >> 7;
    const int s   = threadIdx.x;   // 0..319
    const float e = g_copy[(size_t)row * LSRC + s];

    int idx;
    if (s < CTXL)            idx = context[b * CTXL + s];
    else if (s < CTXL + STN) idx = loc2glo[tp[b * STN + (s - CTXL)]];
    else                     idx = loc2glo[action[b * STN + (s - CTXL - STN)]];

    atomicAdd(out + (size_t)row * NV + idx, e);
}

// ---------------------------------------------------------------------------
// Kernel 4: normalize out by per-row sums
// ---------------------------------------------------------------------------
__global__ __launch_bounds__(256)
void norm_kernel(float* __restrict__ out)
{
    const int row = blockIdx.y;
    const int i = blockIdx.x * 256 + threadIdx.x;   // float4 index
    if (i >= NV / 4) return;
    const float inv = 1.0f / g_rsum[row];
    float4 v = *(const float4*)(out + (size_t)row * NV + i * 4);
    v.x *= inv; v.y *= inv; v.z *= inv; v.w *= inv;
    *(float4*)(out + (size_t)row * NV + i * 4) = v;
}

// ---------------------------------------------------------------------------
extern "C" void kernel_launch(void* const* d_in, const int* in_sizes, int n_in,
                              void* d_out, int out_size)
{
    const float* dec     = (const float*)d_in[0];  // (8,128,512)
    const float* src     = (const float*)d_in[1];  // (8,320,512)
    const float* W       = (const float*)d_in[2];  // (512,32000)
    const float* bgen    = (const float*)d_in[3];  // (32000,)
    const int*   mask    = (const int*)d_in[4];    // (8,1,320)
    const int*   context = (const int*)d_in[5];    // (8,256)
    const int*   tp      = (const int*)d_in[6];    // (8,32)
    const int*   action  = (const int*)d_in[7];    // (8,32)
    const int*   loc2glo = (const int*)d_in[8];    // (4096,)
    float*       out     = (float*)d_out;          // (8,128,32000)

    zero_rsum_kernel<<<NROWS / 256, 256>>>();
    copy_logit_kernel<<<dim3(5, 2, 8), 256>>>(dec, src, mask);
    gen_gemm_kernel<<<dim3(8, 250), 512>>>(dec, W, bgen, out);
    scatter_kernel<<<NROWS, 320>>>(context, tp, action, loc2glo, out);
    norm_kernel<<<dim3(32, NROWS), 256>>>(out);
}

// round 5
// speedup vs baseline: 1.8350x; 1.4556x over previous
#include <cuda_runtime.h>
#include <cuda_bf16.h>
#include <math.h>
#include <stdint.h>

#define NROWS 1024
#define NV    32000
#define LSRC  320
#define CTXL  256
#define STN   32
#define HDIM  512
#define SCALE 0.04419417382415922f   // 1/sqrt(512)

__device__ __nv_bfloat16 g_Wbf[(size_t)HDIM * NV];   // 32.8 MB
__device__ __nv_bfloat16 g_Abf[(size_t)NROWS * HDIM];
__device__ float g_copy[(size_t)NROWS * LSRC];
__device__ float g_rsum[NROWS];

// ---------------------------------------------------------------------------
// PTX helpers
// ---------------------------------------------------------------------------
__device__ __forceinline__ uint32_t smem_u32(const void* p) {
    return (uint32_t)__cvta_generic_to_shared(p);
}
__device__ __forceinline__ void cp_async16(uint32_t dst, const void* src) {
    asm volatile("cp.async.cg.shared.global [%0], [%1], 16;\n" :: "r"(dst), "l"(src));
}
__device__ __forceinline__ void cp_commit() {
    asm volatile("cp.async.commit_group;\n");
}
template <int N> __device__ __forceinline__ void cp_wait() {
    asm volatile("cp.async.wait_group %0;\n" :: "n"(N));
}
__device__ __forceinline__ void ldsm_x4(uint32_t* r, uint32_t a) {
    asm volatile("ldmatrix.sync.aligned.m8n8.x4.shared.b16 {%0,%1,%2,%3}, [%4];\n"
                 : "=r"(r[0]), "=r"(r[1]), "=r"(r[2]), "=r"(r[3]) : "r"(a));
}
__device__ __forceinline__ void ldsm_x4_t(uint32_t* r, uint32_t a) {
    asm volatile("ldmatrix.sync.aligned.m8n8.x4.trans.shared.b16 {%0,%1,%2,%3}, [%4];\n"
                 : "=r"(r[0]), "=r"(r[1]), "=r"(r[2]), "=r"(r[3]) : "r"(a));
}
__device__ __forceinline__ void mma16816(float* c, const uint32_t* a, const uint32_t* b) {
    asm volatile(
        "mma.sync.aligned.m16n8k16.row.col.f32.bf16.bf16.f32 "
        "{%0,%1,%2,%3}, {%4,%5,%6,%7}, {%8,%9}, {%0,%1,%2,%3};\n"
        : "+f"(c[0]), "+f"(c[1]), "+f"(c[2]), "+f"(c[3])
        : "r"(a[0]), "r"(a[1]), "r"(a[2]), "r"(a[3]),
          "r"(b[0]), "r"(b[1]));
}

// ---------------------------------------------------------------------------
// Kernel 0: convert W + dec to bf16, zero row sums.
// ---------------------------------------------------------------------------
#define NW4 ((HDIM * (size_t)NV) / 4)     // 4,096,000 float4
#define NA4 ((NROWS * (size_t)HDIM) / 4)  // 131,072 float4

__global__ __launch_bounds__(256)
void convert_kernel(const float* __restrict__ W, const float* __restrict__ dec)
{
    const size_t gid = (size_t)blockIdx.x * 256 + threadIdx.x;
    if (gid < NROWS) g_rsum[gid] = 0.f;
    if (gid < NW4) {
        float4 v = ((const float4*)W)[gid];
        uint2 o;
        o.x = __nv_bfloat162_raw(__floats2bfloat162_rn(v.x, v.y)).x |
              ((uint32_t)__nv_bfloat162_raw(__floats2bfloat162_rn(v.x, v.y)).y << 16);
        // simpler: build via reinterpret
        __nv_bfloat162 p0 = __floats2bfloat162_rn(v.x, v.y);
        __nv_bfloat162 p1 = __floats2bfloat162_rn(v.z, v.w);
        o.x = *(uint32_t*)&p0;
        o.y = *(uint32_t*)&p1;
        ((uint2*)g_Wbf)[gid] = o;
    } else if (gid < NW4 + NA4) {
        const size_t i = gid - NW4;
        float4 v = ((const float4*)dec)[i];
        __nv_bfloat162 p0 = __floats2bfloat162_rn(v.x, v.y);
        __nv_bfloat162 p1 = __floats2bfloat162_rn(v.z, v.w);
        uint2 o = {*(uint32_t*)&p0, *(uint32_t*)&p1};
        ((uint2*)g_Abf)[i] = o;
    }
}

// ---------------------------------------------------------------------------
// Kernel 1 (fused): gen GEMM (+exp +row-sum) for blockIdx.y < 250,
//                   copy-logit blocks for blockIdx.y in [250, 260).
// GEMM: BM=128 BN=128 BK=32, 512 thr (16 warps 4x4, warp tile 32x32),
//       cp.async 3-stage pipeline, ldmatrix fragments.
// ---------------------------------------------------------------------------
#define BK 32
#define A_BYTES 10240      // 128 rows * 80 B (32 bf16 + 8 pad)
#define B_BYTES 8704       // 32 rows * 272 B (128 bf16 + 8 pad)
#define STAGE_B (A_BYTES + B_BYTES)   // 18944
#define SMEM_TOTAL (3 * STAGE_B)      // 56832

extern __shared__ char dynsmem[];

__global__ __launch_bounds__(512, 1)
void fused_kernel(const float* __restrict__ dec, const float* __restrict__ src,
                  const float* __restrict__ bias, const int* __restrict__ mask,
                  float* __restrict__ out)
{
    const int tid = threadIdx.x;

    if (blockIdx.y < 250) {
        // =================== GEMM path ===================
        const __nv_bfloat16* Abf = g_Abf;
        const __nv_bfloat16* Wbf = g_Wbf;
        const int warp = tid >> 5, lane = tid & 31;
        const int m0 = blockIdx.x * 128;
        const int n0 = blockIdx.y * 128;
        const int wm = (warp >> 2) * 32;
        const int wn = (warp & 3) * 32;

        const uint32_t aU = smem_u32(dynsmem);
        const uint32_t bU = aU + A_BYTES;

        // cp.async load mappings
        const int la_m = tid >> 2, la_c = tid & 3;     // A: 128 rows x 4 chunks
        const int lb_k = tid >> 4, lb_c = tid & 15;    // B: 32 rows x 16 chunks
        const __nv_bfloat16* aSrcBase = Abf + (size_t)(m0 + la_m) * HDIM + la_c * 8;
        const __nv_bfloat16* bSrcBase = Wbf + (size_t)lb_k * NV + n0 + lb_c * 8;
        const uint32_t aDst = aU + la_m * 80 + la_c * 16;
        const uint32_t bDst = bU + lb_k * 272 + lb_c * 16;

        // prologue: stages 0,1
        #pragma unroll
        for (int s = 0; s < 2; ++s) {
            cp_async16(aDst + s * STAGE_B, aSrcBase + s * BK);
            cp_async16(bDst + s * STAGE_B, bSrcBase + (size_t)s * BK * NV);
            cp_commit();
        }

        float acc[2][4][4];
        #pragma unroll
        for (int i = 0; i < 2; ++i)
            #pragma unroll
            for (int j = 0; j < 4; ++j)
                #pragma unroll
                for (int q = 0; q < 4; ++q) acc[i][j][q] = 0.f;

        const int KT = HDIM / BK;   // 16
        for (int kt = 0; kt < KT; ++kt) {
            if (kt < KT - 2) cp_wait<1>(); else cp_wait<0>();
            __syncthreads();

            // issue load for kt+2 into freed slot
            if (kt + 2 < KT) {
                const int s = (kt + 2) % 3;
                cp_async16(aDst + s * STAGE_B, aSrcBase + (kt + 2) * BK);
                cp_async16(bDst + s * STAGE_B, bSrcBase + (size_t)(kt + 2) * BK * NV);
            }
            cp_commit();   // commit even if empty to keep group counting uniform

            const int st = kt % 3;
            const uint32_t aS = aU + st * STAGE_B;
            const uint32_t bS = bU + st * STAGE_B;

            #pragma unroll
            for (int kk = 0; kk < 2; ++kk) {
                uint32_t af[2][4], bfr[4][2];
                #pragma unroll
                for (int mi = 0; mi < 2; ++mi) {
                    uint32_t addr = aS + (wm + mi * 16 + (lane & 15)) * 80
                                       + kk * 32 + (lane >> 4) * 16;
                    ldsm_x4(af[mi], addr);
                }
                #pragma unroll
                for (int g = 0; g < 2; ++g) {
                    uint32_t r[4];
                    uint32_t addr = bS + (kk * 16 + (lane & 15)) * 272
                                       + wn * 2 + g * 32 + (lane >> 4) * 16;
                    ldsm_x4_t(r, addr);
                    bfr[g * 2][0] = r[0]; bfr[g * 2][1] = r[1];
                    bfr[g * 2 + 1][0] = r[2]; bfr[g * 2 + 1][1] = r[3];
                }
                #pragma unroll
                for (int mi = 0; mi < 2; ++mi)
                    #pragma unroll
                    for (int ni = 0; ni < 4; ++ni)
                        mma16816(acc[mi][ni], af[mi], bfr[ni]);
            }
            __syncthreads();
        }

        // epilogue: exp((acc + bias) * SCALE) -> out ; partial row sums
        const int tg = lane & 3, gr = lane >> 2;
        #pragma unroll
        for (int mi = 0; mi < 2; ++mi) {
            const int row = m0 + wm + mi * 16 + gr;
            float rs0 = 0.f, rs1 = 0.f;
            #pragma unroll
            for (int ni = 0; ni < 4; ++ni) {
                const int col = n0 + wn + ni * 8 + tg * 2;
                const float b0 = bias[col], b1 = bias[col + 1];
                float e00 = __expf((acc[mi][ni][0] + b0) * SCALE);
                float e01 = __expf((acc[mi][ni][1] + b1) * SCALE);
                float e10 = __expf((acc[mi][ni][2] + b0) * SCALE);
                float e11 = __expf((acc[mi][ni][3] + b1) * SCALE);
                rs0 += e00 + e01;
                rs1 += e10 + e11;
                float2 v0 = {e00, e01}, v1 = {e10, e11};
                *(float2*)(out + (size_t)row * NV + col)       = v0;
                *(float2*)(out + (size_t)(row + 8) * NV + col) = v1;
            }
            rs0 += __shfl_xor_sync(0xffffffffu, rs0, 1);
            rs0 += __shfl_xor_sync(0xffffffffu, rs0, 2);
            rs1 += __shfl_xor_sync(0xffffffffu, rs1, 1);
            rs1 += __shfl_xor_sync(0xffffffffu, rs1, 2);
            if (tg == 0) {
                atomicAdd(&g_rsum[row], rs0);
                atomicAdd(&g_rsum[row + 8], rs1);
            }
        }
    } else {
        // =================== copy-logit path ===================
        // 80 blocks: cid -> (st 0..4, lt 0..1, b 0..7); tile 64 l-rows x 64 s-cols
        const int cid = (blockIdx.y - 250) * 8 + blockIdx.x;   // 0..79
        const int st = cid % 5;
        const int r2 = cid / 5;
        const int lt = r2 & 1, b = r2 >> 1;

        float* sA2 = (float*)dynsmem;        // [2][64][17]
        float* sB2 = sA2 + 2176;             // [2][64][17]
        #define SA2(u,r,c) sA2[(u) * 1088 + (r) * 17 + (c)]
        #define SB2(u,r,c) sB2[(u) * 1088 + (r) * 17 + (c)]

        const int lr = tid >> 3;            // 0..63
        const int lc = (tid & 7) * 2;       // 0..14
        const int ty = tid >> 5;            // 0..15 (= warp)
        const int tx = tid & 31;            // 0..31

        const float* Ag = dec + (size_t)(b * 128 + lt * 64) * HDIM;
        const float* Bg = src + (size_t)(b * LSRC + st * 64) * HDIM;

        float2 ra = *(const float2*)(Ag + (size_t)lr * HDIM + lc);
        float2 rb = *(const float2*)(Bg + (size_t)lr * HDIM + lc);
        SA2(0, lr, lc) = ra.x; SA2(0, lr, lc + 1) = ra.y;
        SB2(0, lr, lc) = rb.x; SB2(0, lr, lc + 1) = rb.y;
        __syncthreads();

        float acc[4][2] = {};

        for (int kt = 0; kt < 32; ++kt) {
            const int buf = kt & 1;
            if (kt < 31) {
                const int k0 = (kt + 1) * 16;
                ra = *(const float2*)(Ag + (size_t)lr * HDIM + k0 + lc);
                rb = *(const float2*)(Bg + (size_t)lr * HDIM + k0 + lc);
            }
            #pragma unroll
            for (int k = 0; k < 16; ++k) {
                float a0 = SA2(buf, ty * 4 + 0, k);
                float a1 = SA2(buf, ty * 4 + 1, k);
                float a2 = SA2(buf, ty * 4 + 2, k);
                float a3 = SA2(buf, ty * 4 + 3, k);
                float b0 = SB2(buf, tx * 2 + 0, k);
                float b1 = SB2(buf, tx * 2 + 1, k);
                acc[0][0] += a0 * b0; acc[0][1] += a0 * b1;
                acc[1][0] += a1 * b0; acc[1][1] += a1 * b1;
                acc[2][0] += a2 * b0; acc[2][1] += a2 * b1;
                acc[3][0] += a3 * b0; acc[3][1] += a3 * b1;
            }
            if (kt < 31) {
                const int nb = 1 - buf;
                SA2(nb, lr, lc) = ra.x; SA2(nb, lr, lc + 1) = ra.y;
                SB2(nb, lr, lc) = rb.x; SB2(nb, lr, lc + 1) = rb.y;
            }
            __syncthreads();
        }

        #pragma unroll
        for (int i = 0; i < 4; ++i) {
            const int row = b * 128 + lt * 64 + ty * 4 + i;
            float rs = 0.f;
            #pragma unroll
            for (int j = 0; j < 2; ++j) {
                const int sg = st * 64 + tx * 2 + j;
                float e = (mask[b * LSRC + sg] == 0) ? 0.f : __expf(acc[i][j] * SCALE);
                g_copy[(size_t)row * LSRC + sg] = e;
                rs += e;
            }
            #pragma unroll
            for (int off = 16; off > 0; off >>= 1)
                rs += __shfl_xor_sync(0xffffffffu, rs, off);
            if (tx == 0) atomicAdd(&g_rsum[row], rs);
        }
        #undef SA2
        #undef SB2
    }
}

// ---------------------------------------------------------------------------
// Kernel 2: normalize + scatter (one block per row; block-local ordering).
// ---------------------------------------------------------------------------
__global__ __launch_bounds__(320)
void norm_scatter_kernel(const int* __restrict__ context, const int* __restrict__ tp,
                         const int* __restrict__ action, const int* __restrict__ loc2glo,
                         float* __restrict__ out)
{
    const int row = blockIdx.x;
    const int t   = threadIdx.x;   // 0..319
    const float inv = 1.0f / g_rsum[row];

    float4* o4 = (float4*)(out + (size_t)row * NV);
    #pragma unroll 5
    for (int i = t; i < NV / 4; i += 320) {
        float4 v = o4[i];
        v.x *= inv; v.y *= inv; v.z *= inv; v.w *= inv;
        o4[i] = v;
    }
    __syncthreads();

    const int b = row >> 7;
    const float e = g_copy[(size_t)row * LSRC + t] * inv;
    int idx;
    if (t < CTXL)            idx = context[b * CTXL + t];
    else if (t < CTXL + STN) idx = loc2glo[tp[b * STN + (t - CTXL)]];
    else                     idx = loc2glo[action[b * STN + (t - CTXL - STN)]];
    atomicAdd(out + (size_t)row * NV + idx, e);
}

// ---------------------------------------------------------------------------
extern "C" void kernel_launch(void* const* d_in, const int* in_sizes, int n_in,
                              void* d_out, int out_size)
{
    const float* dec     = (const float*)d_in[0];  // (8,128,512)
    const float* src     = (const float*)d_in[1];  // (8,320,512)
    const float* W       = (const float*)d_in[2];  // (512,32000)
    const float* bgen    = (const float*)d_in[3];  // (32000,)
    const int*   mask    = (const int*)d_in[4];    // (8,1,320)
    const int*   context = (const int*)d_in[5];    // (8,256)
    const int*   tp      = (const int*)d_in[6];    // (8,32)
    const int*   action  = (const int*)d_in[7];    // (8,32)
    const int*   loc2glo = (const int*)d_in[8];    // (4096,)
    float*       out     = (float*)d_out;          // (8,128,32000)

    static bool attr_set = false;
    if (!attr_set) {
        cudaFuncSetAttribute(fused_kernel,
                             cudaFuncAttributeMaxDynamicSharedMemorySize, SMEM_TOTAL);
        attr_set = true;
    }

    const size_t nconv = NW4 + NA4;
    convert_kernel<<<(unsigned)((nconv + 255) / 256), 256>>>(W, dec);
    fused_kernel<<<dim3(8, 260), 512, SMEM_TOTAL>>>(dec, src, bgen, mask, out);
    norm_scatter_kernel<<<NROWS, 320>>>(context, tp, action, loc2glo, out);
}